// round 12
// baseline (speedup 1.0000x reference)
#include <cuda_runtime.h>
#include <cuda_fp16.h>
#include <cstdint>
#include <cstddef>

// ---------------------------------------------------------------------------
// Problem constants
// ---------------------------------------------------------------------------
#define B_SZ   4
#define C_IN   512
#define TD3    1536          // 3*512
#define HH     64
#define WW     64
#define NPIX   4096          // 64*64
#define NGRP   192
#define NHEAD  128
#define EPS_ATT 1e-15f
#define EPS_BN  1e-5f

#define GSTAGES 3
#define ABYTES  8192                  // one operand chunk (128x32 or 32x128 fp16)
#define STAGE_BYTES (4 * ABYTES)      // Ah, Al, Bh, Bl
#define DYN_SMEM (GSTAGES * STAGE_BYTES)   // 96 KB  (x2 CTAs = 192 KB/SM)

// ---------------------------------------------------------------------------
// Scratch (device globals; no allocation allowed)
// ---------------------------------------------------------------------------
__device__ float   g_qkv[(size_t)B_SZ * TD3 * NPIX];    // fp32 [b][ch][n]
__device__ float   g_y  [(size_t)B_SZ * TD3 * NPIX];    // fp32 [b][ch][n]
__device__ float   g_tmp[(size_t)B_SZ * 512 * NPIX];    // GEMM2a partial
__device__ __half  g_xh [(size_t)B_SZ * C_IN * NPIX];   // fp16 hi [b][c][n]
__device__ __half  g_xl [(size_t)B_SZ * C_IN * NPIX];   // fp16 lo
__device__ __half  g_ath[(size_t)B_SZ * 1024 * NPIX];   // att hi [b][ch][n]
__device__ __half  g_atl[(size_t)B_SZ * 1024 * NPIX];   // att lo
__device__ __half  g_wqh[TD3 * C_IN];
__device__ __half  g_wql[TD3 * C_IN];
__device__ __half  g_wph[512 * 1024];
__device__ __half  g_wpl[512 * 1024];

// ---------------------------------------------------------------------------
// helpers
// ---------------------------------------------------------------------------
__device__ __forceinline__ void ldsm_x4(uint32_t* r, uint32_t addr) {
    asm volatile("ldmatrix.sync.aligned.m8n8.x4.shared.b16 {%0,%1,%2,%3}, [%4];"
        : "=r"(r[0]), "=r"(r[1]), "=r"(r[2]), "=r"(r[3]) : "r"(addr));
}
__device__ __forceinline__ void ldsm_x4_t(uint32_t* r, uint32_t addr) {
    asm volatile("ldmatrix.sync.aligned.m8n8.x4.trans.shared.b16 {%0,%1,%2,%3}, [%4];"
        : "=r"(r[0]), "=r"(r[1]), "=r"(r[2]), "=r"(r[3]) : "r"(addr));
}
__device__ __forceinline__ void mma_f16(float* c, const uint32_t* a, const uint32_t* b) {
    asm volatile("mma.sync.aligned.m16n8k16.row.col.f32.f16.f16.f32 "
        "{%0,%1,%2,%3}, {%4,%5,%6,%7}, {%8,%9}, {%0,%1,%2,%3};"
        : "+f"(c[0]), "+f"(c[1]), "+f"(c[2]), "+f"(c[3])
        : "r"(a[0]), "r"(a[1]), "r"(a[2]), "r"(a[3]), "r"(b[0]), "r"(b[1]));
}
__device__ __forceinline__ void cp16(uint32_t smem, const void* g) {
    asm volatile("cp.async.cg.shared.global [%0], [%1], 16;" :: "r"(smem), "l"(g));
}
__device__ __forceinline__ void cp_commit() { asm volatile("cp.async.commit_group;"); }
template <int N>
__device__ __forceinline__ void cp_wait() { asm volatile("cp.async.wait_group %0;" :: "n"(N)); }

// byte offsets within one 8KB chunk
__device__ __forceinline__ uint32_t swA(int row, int ch) {      // 128 rows x 64B
    return (uint32_t)(row * 64 + ((ch ^ ((row >> 1) & 3)) << 4));
}
__device__ __forceinline__ uint32_t swB(int k, int ch) {        // 32 rows x 256B
    return (uint32_t)(k * 256 + ((ch ^ (k & 7)) << 4));
}

// ---------------------------------------------------------------------------
// fp16 3-term split tensor-core GEMM (generic strides):
//   C[b] = Ah*Bh + Ah*Bl + Al*Bh  [+ Tmp]  (A MxK row stride lda, shared;
//   B per-batch, row stride N, batch stride bbatch; C fp32 MxN per batch)
// Block 128x128, K-tile 32, 128 threads (4 warps, warp tile 64x64).
// 3-stage cp.async ring, 2 CTAs/SM, single barrier per K-tile.
// ---------------------------------------------------------------------------
template <bool EPI, bool ADD>
__global__ __launch_bounds__(128, 2)
void mma_gemm(const __half* __restrict__ Ah, const __half* __restrict__ Al,
              const __half* __restrict__ Bhg, const __half* __restrict__ Blg,
              float* __restrict__ Cg, const float* __restrict__ Tmp,
              int M, int N, int K, int lda, long long bbatch,
              const float* __restrict__ gamma, const float* __restrict__ beta,
              const float* __restrict__ mean,  const float* __restrict__ var)
{
    extern __shared__ __align__(16) char smem[];
    const uint32_t sbase = (uint32_t)__cvta_generic_to_shared(smem);

    const int tid  = threadIdx.x;
    const int lane = tid & 31;
    const int wid  = tid >> 5;
    const int warp_m = wid >> 1;   // 0..1  (64 rows)
    const int warp_n = wid & 1;    // 0..1  (64 cols)
    const int m0 = blockIdx.y * 128;
    const int n0 = blockIdx.x * 128;

    const __half* Bh = Bhg + (size_t)blockIdx.z * bbatch;
    const __half* Bl = Blg + (size_t)blockIdx.z * bbatch;
    float*       Cp  = Cg  + (size_t)blockIdx.z * M * N;
    const float* Tp  = ADD ? (Tmp + (size_t)blockIdx.z * M * N) : nullptr;

    const int arow = tid >> 2, ach = tid & 3;    // 4 rows each (+0,+32,+64,+96)
    const int bk   = tid >> 4, bch = tid & 15;   // 4 k each   (+0,+8,+16,+24)

    float acc[4][8][4];
#pragma unroll
    for (int i = 0; i < 4; i++)
#pragma unroll
        for (int j = 0; j < 8; j++)
#pragma unroll
            for (int r = 0; r < 4; r++) acc[i][j][r] = 0.f;

    const int nkt = K / 32;

    auto prefetch = [&](int kt) {
        const uint32_t st = sbase + (kt % GSTAGES) * STAGE_BYTES;
#pragma unroll
        for (int i = 0; i < 4; i++) {
            size_t aoff = (size_t)(m0 + arow + i * 32) * lda + kt * 32 + ach * 8;
            uint32_t ao = swA(arow + i * 32, ach);
            cp16(st + ao,          Ah + aoff);
            cp16(st + ABYTES + ao, Al + aoff);
            size_t boff = (size_t)(kt * 32 + bk + i * 8) * N + n0 + bch * 8;
            uint32_t bo = swB(bk + i * 8, bch);
            cp16(st + 2 * ABYTES + bo, Bh + boff);
            cp16(st + 3 * ABYTES + bo, Bl + boff);
        }
        cp_commit();
    };

    prefetch(0);
    prefetch(1);

    for (int kt = 0; kt < nkt; ++kt) {
        cp_wait<GSTAGES - 2>();
        __syncthreads();

        const uint32_t st  = sbase + (kt % GSTAGES) * STAGE_BYTES;
        const uint32_t aAh = st;
        const uint32_t aAl = st + ABYTES;
        const uint32_t aBh = st + 2 * ABYTES;
        const uint32_t aBl = st + 3 * ABYTES;

#pragma unroll
        for (int kk = 0; kk < 2; ++kk) {
            const int kcol = kk * 16;
            uint32_t bh[4][4], bl[4][4];
#pragma unroll
            for (int p = 0; p < 4; p++) {
                int k = kcol + ((lane >> 3) & 1) * 8 + (lane & 7);
                int n = warp_n * 64 + p * 16 + (lane >> 4) * 8;
                uint32_t off = swB(k, n >> 3);
                ldsm_x4_t(bh[p], aBh + off);
                ldsm_x4_t(bl[p], aBl + off);
            }
#pragma unroll
            for (int mf = 0; mf < 4; mf++) {
                uint32_t ah[4], al[4];
                int row = warp_m * 64 + mf * 16 + ((lane >> 3) & 1) * 8 + (lane & 7);
                int ch  = (kcol >> 3) + (lane >> 4);
                uint32_t off = swA(row, ch);
                ldsm_x4(ah, aAh + off);
                ldsm_x4(al, aAl + off);
#pragma unroll
                for (int nf = 0; nf < 8; nf++) {
                    const uint32_t* ph = &bh[nf >> 1][(nf & 1) * 2];
                    const uint32_t* pl = &bl[nf >> 1][(nf & 1) * 2];
                    mma_f16(acc[mf][nf], ah, ph);
                    mma_f16(acc[mf][nf], ah, pl);
                    mma_f16(acc[mf][nf], al, ph);
                }
            }
            if (kk == 0) {
                if (kt + GSTAGES - 1 < nkt) prefetch(kt + GSTAGES - 1);
                else cp_commit();
            }
        }
        // single barrier per K-tile: next iteration's top barrier orders reuse
    }

    // epilogue
#pragma unroll
    for (int mf = 0; mf < 4; mf++) {
        int r0 = m0 + warp_m * 64 + mf * 16 + (lane >> 2);
        float s0 = 1.f, t0 = 0.f, s1 = 1.f, t1 = 0.f;
        if (EPI) {
            float iv0 = rsqrtf(var[r0] + EPS_BN);
            s0 = gamma[r0] * iv0; t0 = beta[r0] - mean[r0] * s0;
            float iv1 = rsqrtf(var[r0 + 8] + EPS_BN);
            s1 = gamma[r0 + 8] * iv1; t1 = beta[r0 + 8] - mean[r0 + 8] * s1;
        }
#pragma unroll
        for (int nf = 0; nf < 8; nf++) {
            int c = n0 + warp_n * 64 + nf * 8 + (lane & 3) * 2;
            float a0 = acc[mf][nf][0], a1 = acc[mf][nf][1];
            float a2 = acc[mf][nf][2], a3 = acc[mf][nf][3];
            if (ADD) {
                float2 u0 = *(const float2*)(Tp + (size_t)r0 * N + c);
                float2 u1 = *(const float2*)(Tp + (size_t)(r0 + 8) * N + c);
                a0 += u0.x; a1 += u0.y; a2 += u1.x; a3 += u1.y;
            }
            float2 v0, v1;
            if (EPI) {
                v0 = make_float2(a0 * s0 + t0, a1 * s0 + t0);
                v1 = make_float2(a2 * s1 + t1, a3 * s1 + t1);
            } else {
                v0 = make_float2(a0, a1);
                v1 = make_float2(a2, a3);
            }
            *(float2*)(Cp + (size_t)r0 * N + c)       = v0;
            *(float2*)(Cp + (size_t)(r0 + 8) * N + c) = v1;
        }
    }
}

// ---------------------------------------------------------------------------
// fp32 -> fp16 hi/lo split (x4)
// ---------------------------------------------------------------------------
__global__ void split_kernel(const float* __restrict__ in,
                             __half* __restrict__ h, __half* __restrict__ l, int n4)
{
    int i = blockIdx.x * 256 + threadIdx.x;
    if (i >= n4) return;
    float4 v = ((const float4*)in)[i];
    __half h0 = __float2half(v.x), h1 = __float2half(v.y);
    __half h2 = __float2half(v.z), h3 = __float2half(v.w);
    ((__half2*)h)[i * 2]     = __halves2half2(h0, h1);
    ((__half2*)h)[i * 2 + 1] = __halves2half2(h2, h3);
    ((__half2*)l)[i * 2]     = __halves2half2(__float2half(v.x - __half2float(h0)),
                                              __float2half(v.y - __half2float(h1)));
    ((__half2*)l)[i * 2 + 1] = __halves2half2(__float2half(v.z - __half2float(h2)),
                                              __float2half(v.w - __half2float(h3)));
}

// ---------------------------------------------------------------------------
// Fused depthwise 5x5 (pad 2) + grouped 8x8 pointwise. 64x8 pixel tiles,
// float4 interior loads, padded smem rows.
// ---------------------------------------------------------------------------
__global__ __launch_bounds__(256)
void dwpw_kernel(const float* __restrict__ qkv, const float* __restrict__ w_dw,
                 const float* __restrict__ w_pw, float* __restrict__ y)
{
    __shared__ float tile[8][12][72];   // data at cols [4..67], zeros elsewhere
    __shared__ float wdw[8][25];
    __shared__ float wpw[64];

    const int b   = blockIdx.z / NGRP;
    const int g   = blockIdx.z % NGRP;
    const int ch0 = g * 8;
    const int h0  = blockIdx.y * 8;
    const int tid = threadIdx.y * 32 + threadIdx.x;

    for (int i = tid; i < 200; i += 256)
        wdw[i / 25][i % 25] = w_dw[(ch0 + i / 25) * 25 + i % 25];
    if (tid < 64) wpw[tid] = w_pw[g * 64 + tid];

    for (int i = tid; i < 8 * 12 * 8; i += 256) {
        int c = i / 96;
        int r = (i / 8) % 12;
        int e = i % 8;
        int col = (e < 4) ? e : (64 + e);
        tile[c][r][col] = 0.f;
    }

    const float* base = qkv + ((size_t)b * TD3 + ch0) * NPIX;
    for (int i = tid; i < 8 * 12 * 16; i += 256) {
        int c   = i / 192;
        int rem = i % 192;
        int r   = rem / 16;
        int v4  = rem % 16;
        int gh  = h0 - 2 + r;
        float4 val = make_float4(0.f, 0.f, 0.f, 0.f);
        if (gh >= 0 && gh < HH)
            val = ((const float4*)(base + (size_t)c * NPIX + gh * WW))[v4];
        *(float4*)&tile[c][r][4 + v4 * 4] = val;
    }
    __syncthreads();

    const int tx = threadIdx.x, ty = threadIdx.y;
    float dw[2][8];
#pragma unroll
    for (int half = 0; half < 2; half++) {
        int x = tx + half * 32;
#pragma unroll
        for (int c = 0; c < 8; c++) {
            float s = 0.f;
#pragma unroll
            for (int i = 0; i < 5; i++)
#pragma unroll
                for (int j = 0; j < 5; j++)
                    s += tile[c][ty + i][x + j + 2] * wdw[c][i * 5 + j];
            dw[half][c] = s;
        }
    }

    float* obase = y + ((size_t)b * TD3 + ch0) * NPIX + (h0 + ty) * WW;
#pragma unroll
    for (int o = 0; o < 8; o++) {
        float s0 = 0.f, s1 = 0.f;
#pragma unroll
        for (int i = 0; i < 8; i++) {
            s0 += dw[0][i] * wpw[o * 8 + i];
            s1 += dw[1][i] * wpw[o * 8 + i];
        }
        obase[(size_t)o * NPIX + tx]      = s0;
        obase[(size_t)o * NPIX + tx + 32] = s1;
    }
}

// ---------------------------------------------------------------------------
// Linear attention over 64 heads from one source tensor, float4-vectorized.
// ---------------------------------------------------------------------------
__global__ __launch_bounds__(256)
void attn_kernel(const float* __restrict__ src,
                 __half* __restrict__ att_h, __half* __restrict__ att_l,
                 int ch_out_base)
{
    const int b    = blockIdx.x >> 6;
    const int hloc = blockIdx.x & 63;
    const int tid  = threadIdx.x;

    const float* base = src + ((size_t)b * TD3 + hloc * 24) * NPIX;

    float acc[72];
#pragma unroll
    for (int i = 0; i < 72; i++) acc[i] = 0.f;

    for (int n4 = tid; n4 < NPIX / 4; n4 += 256) {
        float4 kk[8], vv[8];
#pragma unroll
        for (int e = 0; e < 8; e++) {
            float4 t = ((const float4*)(base + (size_t)(8 + e) * NPIX))[n4];
            kk[e] = make_float4(fmaxf(t.x, 0.f), fmaxf(t.y, 0.f),
                                fmaxf(t.z, 0.f), fmaxf(t.w, 0.f));
        }
#pragma unroll
        for (int d = 0; d < 8; d++)
            vv[d] = ((const float4*)(base + (size_t)(16 + d) * NPIX))[n4];
#pragma unroll
        for (int d = 0; d < 8; d++)
#pragma unroll
            for (int e = 0; e < 8; e++)
                acc[d * 8 + e] += vv[d].x * kk[e].x + vv[d].y * kk[e].y
                                + vv[d].z * kk[e].z + vv[d].w * kk[e].w;
#pragma unroll
        for (int e = 0; e < 8; e++)
            acc[64 + e] += kk[e].x + kk[e].y + kk[e].z + kk[e].w;
    }

    __shared__ float red[8][72];
    __shared__ float vk_s[72];
    const int lane = tid & 31, wid = tid >> 5;
#pragma unroll
    for (int i = 0; i < 72; i++) {
        float v = acc[i];
        v += __shfl_down_sync(0xffffffffu, v, 16);
        v += __shfl_down_sync(0xffffffffu, v, 8);
        v += __shfl_down_sync(0xffffffffu, v, 4);
        v += __shfl_down_sync(0xffffffffu, v, 2);
        v += __shfl_down_sync(0xffffffffu, v, 1);
        if (lane == 0) red[wid][i] = v;
    }
    __syncthreads();
    if (tid < 72) {
        float s = 0.f;
#pragma unroll
        for (int w = 0; w < 8; w++) s += red[w][tid];
        vk_s[tid] = s;
    }
    __syncthreads();

    float vk[72];
#pragma unroll
    for (int i = 0; i < 72; i++) vk[i] = vk_s[i];

    const size_t obase = ((size_t)b * 1024 + ch_out_base + hloc * 8) * NPIX;
    for (int n4 = tid; n4 < NPIX / 4; n4 += 256) {
        float4 q[8];
#pragma unroll
        for (int e = 0; e < 8; e++) {
            float4 t = ((const float4*)(base + (size_t)e * NPIX))[n4];
            q[e] = make_float4(fmaxf(t.x, 0.f), fmaxf(t.y, 0.f),
                               fmaxf(t.z, 0.f), fmaxf(t.w, 0.f));
        }
        float4 den = make_float4(0.f, 0.f, 0.f, 0.f);
#pragma unroll
        for (int e = 0; e < 8; e++) {
            den.x += vk[64 + e] * q[e].x; den.y += vk[64 + e] * q[e].y;
            den.z += vk[64 + e] * q[e].z; den.w += vk[64 + e] * q[e].w;
        }
        float4 inv = make_float4(1.f / (den.x + EPS_ATT), 1.f / (den.y + EPS_ATT),
                                 1.f / (den.z + EPS_ATT), 1.f / (den.w + EPS_ATT));
#pragma unroll
        for (int d = 0; d < 8; d++) {
            float4 num = make_float4(0.f, 0.f, 0.f, 0.f);
#pragma unroll
            for (int e = 0; e < 8; e++) {
                num.x += vk[d * 8 + e] * q[e].x; num.y += vk[d * 8 + e] * q[e].y;
                num.z += vk[d * 8 + e] * q[e].z; num.w += vk[d * 8 + e] * q[e].w;
            }
            float o0 = num.x * inv.x, o1 = num.y * inv.y;
            float o2 = num.z * inv.z, o3 = num.w * inv.w;
            __half h0 = __float2half(o0), h1 = __float2half(o1);
            __half h2 = __float2half(o2), h3 = __float2half(o3);
            __half2 hp0 = __halves2half2(h0, h1), hp1 = __halves2half2(h2, h3);
            __half2 lp0 = __halves2half2(__float2half(o0 - __half2float(h0)),
                                         __float2half(o1 - __half2float(h1)));
            __half2 lp1 = __halves2half2(__float2half(o2 - __half2float(h2)),
                                         __float2half(o3 - __half2float(h3)));
            size_t idx = obase + (size_t)d * NPIX + n4 * 4;
            __half2* ph = (__half2*)(att_h + idx);
            __half2* pl = (__half2*)(att_l + idx);
            ph[0] = hp0; ph[1] = hp1;
            pl[0] = lp0; pl[1] = lp1;
        }
    }
}

// ---------------------------------------------------------------------------
// Launch
// ---------------------------------------------------------------------------
extern "C" void kernel_launch(void* const* d_in, const int* in_sizes, int n_in,
                              void* d_out, int out_size)
{
    const float* x      = (const float*)d_in[0];
    const float* w_qkv  = (const float*)d_in[1];
    const float* w_dw   = (const float*)d_in[2];
    const float* w_pw   = (const float*)d_in[3];
    const float* w_proj = (const float*)d_in[4];
    const float* gamma  = (const float*)d_in[5];
    const float* beta   = (const float*)d_in[6];
    const float* mean   = (const float*)d_in[7];
    const float* var    = (const float*)d_in[8];
    float* out = (float*)d_out;

    float *qkv, *yb, *tmp;
    __half *xh, *xl, *ath, *atl, *wqh, *wql, *wph, *wpl;
    cudaGetSymbolAddress((void**)&qkv, g_qkv);
    cudaGetSymbolAddress((void**)&yb,  g_y);
    cudaGetSymbolAddress((void**)&tmp, g_tmp);
    cudaGetSymbolAddress((void**)&xh,  g_xh);
    cudaGetSymbolAddress((void**)&xl,  g_xl);
    cudaGetSymbolAddress((void**)&ath, g_ath);
    cudaGetSymbolAddress((void**)&atl, g_atl);
    cudaGetSymbolAddress((void**)&wqh, g_wqh);
    cudaGetSymbolAddress((void**)&wql, g_wql);
    cudaGetSymbolAddress((void**)&wph, g_wph);
    cudaGetSymbolAddress((void**)&wpl, g_wpl);

    static cudaStream_t s_side = nullptr;
    static cudaEvent_t ev_fork = nullptr, ev_join = nullptr;
    if (!s_side) {
        cudaStreamCreateWithFlags(&s_side, cudaStreamNonBlocking);
        cudaEventCreateWithFlags(&ev_fork, cudaEventDisableTiming);
        cudaEventCreateWithFlags(&ev_join, cudaEventDisableTiming);
        cudaFuncSetAttribute(mma_gemm<false, false>,
            cudaFuncAttributeMaxDynamicSharedMemorySize, DYN_SMEM);
        cudaFuncSetAttribute(mma_gemm<true, true>,
            cudaFuncAttributeMaxDynamicSharedMemorySize, DYN_SMEM);
    }

    const long long bb1 = (long long)C_IN * NPIX;   // x batch stride
    const long long bb2 = (long long)1024 * NPIX;   // att batch stride

    // 0) splits needed by GEMM1 (main stream)
    {
        int n4 = (B_SZ * C_IN * NPIX) / 4;
        split_kernel<<<(n4 + 255) / 256, 256>>>(x, xh, xl, n4);
        n4 = (TD3 * C_IN) / 4;
        split_kernel<<<(n4 + 255) / 256, 256>>>(w_qkv, wqh, wql, n4);
    }
    // w_proj split on side stream (independent; overlaps GEMM1)
    {
        int n4 = (512 * 1024) / 4;
        split_kernel<<<(n4 + 255) / 256, 256, 0, s_side>>>(w_proj, wph, wpl, n4);
    }

    // 1) qkv = w_qkv @ x   (M=1536, N=4096, K=512 per batch), fp32 out
    mma_gemm<false, false><<<dim3(NPIX / 128, TD3 / 128, B_SZ), 128, DYN_SMEM>>>(
        wqh, wql, xh, xl, qkv, nullptr, TD3, NPIX, C_IN, C_IN, bb1,
        nullptr, nullptr, nullptr, nullptr);

    // fork after GEMM1: side stream does attn_lo then GEMM2a (K-half 0)
    cudaEventRecord(ev_fork, 0);
    cudaStreamWaitEvent(s_side, ev_fork, 0);
    attn_kernel<<<B_SZ * 64, 256, 0, s_side>>>(qkv, ath, atl, 0);
    mma_gemm<false, false><<<dim3(NPIX / 128, 512 / 128, B_SZ), 128, DYN_SMEM, s_side>>>(
        wph, wpl, ath, atl, tmp, nullptr, 512, NPIX, 512, 1024, bb2,
        nullptr, nullptr, nullptr, nullptr);
    cudaEventRecord(ev_join, s_side);

    // main stream: dwpw -> attn_hi (concurrent with side)
    dwpw_kernel<<<dim3(1, HH / 8, B_SZ * NGRP), dim3(32, 8)>>>(
        qkv, w_dw, w_pw, yb);
    attn_kernel<<<B_SZ * 64, 256>>>(yb, ath, atl, 512);

    // join, then GEMM2b: K-half 1 + tmp + BN -> out
    cudaStreamWaitEvent(0, ev_join, 0);
    mma_gemm<true, true><<<dim3(NPIX / 128, 512 / 128, B_SZ), 128, DYN_SMEM>>>(
        wph + 512, wpl + 512, ath + (size_t)512 * NPIX, atl + (size_t)512 * NPIX,
        out, tmp, 512, NPIX, 512, 1024, bb2,
        gamma, beta, mean, var);
}

// round 15
// speedup vs baseline: 1.0586x; 1.0586x over previous
#include <cuda_runtime.h>
#include <cuda_fp16.h>
#include <cstdint>
#include <cstddef>

// ---------------------------------------------------------------------------
// Problem constants
// ---------------------------------------------------------------------------
#define B_SZ   4
#define C_IN   512
#define TD3    1536          // 3*512
#define HH     64
#define WW     64
#define NPIX   4096          // 64*64
#define NGRP   192
#define NHEAD  128
#define EPS_ATT 1e-15f
#define EPS_BN  1e-5f

#define GSTAGES 3
#define ABYTES  8192                  // one operand chunk (128x32 or 32x128 fp16)
#define STAGE_BYTES (4 * ABYTES)      // Ah, Al, Bh, Bl
#define DYN_SMEM (GSTAGES * STAGE_BYTES)   // 96 KB  (x2 CTAs = 192 KB/SM)

// ---------------------------------------------------------------------------
// Scratch (device globals; no allocation allowed)
// ---------------------------------------------------------------------------
__device__ float   g_qkv[(size_t)B_SZ * TD3 * NPIX];    // fp32 [b][ch][n]
__device__ float   g_y  [(size_t)B_SZ * TD3 * NPIX];    // fp32 [b][ch][n]
__device__ __half  g_xh [(size_t)B_SZ * C_IN * NPIX];   // fp16 hi [b][c][n]
__device__ __half  g_xl [(size_t)B_SZ * C_IN * NPIX];   // fp16 lo
__device__ __half  g_ath[(size_t)B_SZ * 1024 * NPIX];   // att hi [b][ch][n]
__device__ __half  g_atl[(size_t)B_SZ * 1024 * NPIX];   // att lo
__device__ __half  g_wqh[TD3 * C_IN];
__device__ __half  g_wql[TD3 * C_IN];
__device__ __half  g_wph[512 * 1024];
__device__ __half  g_wpl[512 * 1024];

// ---------------------------------------------------------------------------
// helpers
// ---------------------------------------------------------------------------
__device__ __forceinline__ void ldsm_x4(uint32_t* r, uint32_t addr) {
    asm volatile("ldmatrix.sync.aligned.m8n8.x4.shared.b16 {%0,%1,%2,%3}, [%4];"
        : "=r"(r[0]), "=r"(r[1]), "=r"(r[2]), "=r"(r[3]) : "r"(addr));
}
__device__ __forceinline__ void ldsm_x4_t(uint32_t* r, uint32_t addr) {
    asm volatile("ldmatrix.sync.aligned.m8n8.x4.trans.shared.b16 {%0,%1,%2,%3}, [%4];"
        : "=r"(r[0]), "=r"(r[1]), "=r"(r[2]), "=r"(r[3]) : "r"(addr));
}
__device__ __forceinline__ void mma_f16(float* c, const uint32_t* a, const uint32_t* b) {
    asm volatile("mma.sync.aligned.m16n8k16.row.col.f32.f16.f16.f32 "
        "{%0,%1,%2,%3}, {%4,%5,%6,%7}, {%8,%9}, {%0,%1,%2,%3};"
        : "+f"(c[0]), "+f"(c[1]), "+f"(c[2]), "+f"(c[3])
        : "r"(a[0]), "r"(a[1]), "r"(a[2]), "r"(a[3]), "r"(b[0]), "r"(b[1]));
}
__device__ __forceinline__ void cp16(uint32_t smem, const void* g) {
    asm volatile("cp.async.cg.shared.global [%0], [%1], 16;" :: "r"(smem), "l"(g));
}
__device__ __forceinline__ void cp_commit() { asm volatile("cp.async.commit_group;"); }
template <int N>
__device__ __forceinline__ void cp_wait() { asm volatile("cp.async.wait_group %0;" :: "n"(N)); }

// byte offsets within one 8KB chunk
__device__ __forceinline__ uint32_t swA(int row, int ch) {      // 128 rows x 64B
    return (uint32_t)(row * 64 + ((ch ^ ((row >> 1) & 3)) << 4));
}
__device__ __forceinline__ uint32_t swB(int k, int ch) {        // 32 rows x 256B
    return (uint32_t)(k * 256 + ((ch ^ (k & 7)) << 4));
}

// ---------------------------------------------------------------------------
// fp16 3-term split tensor-core GEMM:
//   C[b] = Ah*Bh + Ah*Bl + Al*Bh   (A = weights MxK, B per-batch KxN)
// Block 128x128, K-tile 32, 128 threads (4 warps, warp tile 64x64).
// 3-stage cp.async ring, 2 CTAs/SM, single barrier per K-tile.
// ---------------------------------------------------------------------------
template <bool EPI>
__global__ __launch_bounds__(128, 2)
void mma_gemm(const __half* __restrict__ Ah, const __half* __restrict__ Al,
              const __half* __restrict__ Bhg, const __half* __restrict__ Blg,
              float* __restrict__ Cg, int M, int N, int K,
              const float* __restrict__ gamma, const float* __restrict__ beta,
              const float* __restrict__ mean,  const float* __restrict__ var)
{
    extern __shared__ __align__(16) char smem[];
    const uint32_t sbase = (uint32_t)__cvta_generic_to_shared(smem);

    const int tid  = threadIdx.x;
    const int lane = tid & 31;
    const int wid  = tid >> 5;
    const int warp_m = wid >> 1;   // 0..1  (64 rows)
    const int warp_n = wid & 1;    // 0..1  (64 cols)
    const int m0 = blockIdx.y * 128;
    const int n0 = blockIdx.x * 128;

    const __half* Bh = Bhg + (size_t)blockIdx.z * K * N;
    const __half* Bl = Blg + (size_t)blockIdx.z * K * N;
    float* Cp = Cg + (size_t)blockIdx.z * M * N;

    const int arow = tid >> 2, ach = tid & 3;    // 4 rows each (+0,+32,+64,+96)
    const int bk   = tid >> 4, bch = tid & 15;   // 4 k each   (+0,+8,+16,+24)

    float acc[4][8][4];
#pragma unroll
    for (int i = 0; i < 4; i++)
#pragma unroll
        for (int j = 0; j < 8; j++)
#pragma unroll
            for (int r = 0; r < 4; r++) acc[i][j][r] = 0.f;

    const int nkt = K / 32;

    auto prefetch = [&](int kt) {
        const uint32_t st = sbase + (kt % GSTAGES) * STAGE_BYTES;
#pragma unroll
        for (int i = 0; i < 4; i++) {
            size_t aoff = (size_t)(m0 + arow + i * 32) * K + kt * 32 + ach * 8;
            uint32_t ao = swA(arow + i * 32, ach);
            cp16(st + ao,          Ah + aoff);
            cp16(st + ABYTES + ao, Al + aoff);
            size_t boff = (size_t)(kt * 32 + bk + i * 8) * N + n0 + bch * 8;
            uint32_t bo = swB(bk + i * 8, bch);
            cp16(st + 2 * ABYTES + bo, Bh + boff);
            cp16(st + 3 * ABYTES + bo, Bl + boff);
        }
        cp_commit();
    };

    prefetch(0);
    prefetch(1);

    for (int kt = 0; kt < nkt; ++kt) {
        cp_wait<GSTAGES - 2>();
        __syncthreads();

        const uint32_t st  = sbase + (kt % GSTAGES) * STAGE_BYTES;
        const uint32_t aAh = st;
        const uint32_t aAl = st + ABYTES;
        const uint32_t aBh = st + 2 * ABYTES;
        const uint32_t aBl = st + 3 * ABYTES;

#pragma unroll
        for (int kk = 0; kk < 2; ++kk) {
            const int kcol = kk * 16;
            uint32_t bh[4][4], bl[4][4];
#pragma unroll
            for (int p = 0; p < 4; p++) {
                int k = kcol + ((lane >> 3) & 1) * 8 + (lane & 7);
                int n = warp_n * 64 + p * 16 + (lane >> 4) * 8;
                uint32_t off = swB(k, n >> 3);
                ldsm_x4_t(bh[p], aBh + off);
                ldsm_x4_t(bl[p], aBl + off);
            }
#pragma unroll
            for (int mf = 0; mf < 4; mf++) {
                uint32_t ah[4], al[4];
                int row = warp_m * 64 + mf * 16 + ((lane >> 3) & 1) * 8 + (lane & 7);
                int ch  = (kcol >> 3) + (lane >> 4);
                uint32_t off = swA(row, ch);
                ldsm_x4(ah, aAh + off);
                ldsm_x4(al, aAl + off);
#pragma unroll
                for (int nf = 0; nf < 8; nf++) {
                    const uint32_t* ph = &bh[nf >> 1][(nf & 1) * 2];
                    const uint32_t* pl = &bl[nf >> 1][(nf & 1) * 2];
                    mma_f16(acc[mf][nf], ah, ph);
                    mma_f16(acc[mf][nf], ah, pl);
                    mma_f16(acc[mf][nf], al, ph);
                }
            }
            if (kk == 0) {
                if (kt + GSTAGES - 1 < nkt) prefetch(kt + GSTAGES - 1);
                else cp_commit();
            }
        }
        // single barrier per K-tile: next iteration's top barrier orders reuse
    }

    // epilogue
#pragma unroll
    for (int mf = 0; mf < 4; mf++) {
        int r0 = m0 + warp_m * 64 + mf * 16 + (lane >> 2);
        float s0 = 1.f, t0 = 0.f, s1 = 1.f, t1 = 0.f;
        if (EPI) {
            float iv0 = rsqrtf(var[r0] + EPS_BN);
            s0 = gamma[r0] * iv0; t0 = beta[r0] - mean[r0] * s0;
            float iv1 = rsqrtf(var[r0 + 8] + EPS_BN);
            s1 = gamma[r0 + 8] * iv1; t1 = beta[r0 + 8] - mean[r0 + 8] * s1;
        }
#pragma unroll
        for (int nf = 0; nf < 8; nf++) {
            int c = n0 + warp_n * 64 + nf * 8 + (lane & 3) * 2;
            float* p0 = Cp + (size_t)r0 * N + c;
            float* p1 = Cp + (size_t)(r0 + 8) * N + c;
            float2 v0, v1;
            if (EPI) {
                v0 = make_float2(acc[mf][nf][0] * s0 + t0, acc[mf][nf][1] * s0 + t0);
                v1 = make_float2(acc[mf][nf][2] * s1 + t1, acc[mf][nf][3] * s1 + t1);
            } else {
                v0 = make_float2(acc[mf][nf][0], acc[mf][nf][1]);
                v1 = make_float2(acc[mf][nf][2], acc[mf][nf][3]);
            }
            *(float2*)p0 = v0;
            *(float2*)p1 = v1;
        }
    }
}

// ---------------------------------------------------------------------------
// fp32 -> fp16 hi/lo split (x4)
// ---------------------------------------------------------------------------
__global__ void split_kernel(const float* __restrict__ in,
                             __half* __restrict__ h, __half* __restrict__ l, int n4)
{
    int i = blockIdx.x * 256 + threadIdx.x;
    if (i >= n4) return;
    float4 v = ((const float4*)in)[i];
    __half h0 = __float2half(v.x), h1 = __float2half(v.y);
    __half h2 = __float2half(v.z), h3 = __float2half(v.w);
    ((__half2*)h)[i * 2]     = __halves2half2(h0, h1);
    ((__half2*)h)[i * 2 + 1] = __halves2half2(h2, h3);
    ((__half2*)l)[i * 2]     = __halves2half2(__float2half(v.x - __half2float(h0)),
                                              __float2half(v.y - __half2float(h1)));
    ((__half2*)l)[i * 2 + 1] = __halves2half2(__float2half(v.z - __half2float(h2)),
                                              __float2half(v.w - __half2float(h3)));
}

// ---------------------------------------------------------------------------
// Fused depthwise 5x5 (pad 2) + grouped 8x8 pointwise.
// 16-row tiles, 4-pixel register strips, LDS.128 tap loads.
// Block: 256 threads = 16 strips (of 4 px) x 16 rows. smem tile 8x20x72.
// ---------------------------------------------------------------------------
__global__ __launch_bounds__(256)
void dwpw_kernel(const float* __restrict__ qkv, const float* __restrict__ w_dw,
                 const float* __restrict__ w_pw, float* __restrict__ y)
{
    __shared__ float tile[8][20][72];   // data cols [4..67], zeros at edges
    __shared__ float wdw[8][25];
    __shared__ float wpw[64];

    const int b   = blockIdx.z / NGRP;
    const int g   = blockIdx.z % NGRP;
    const int ch0 = g * 8;
    const int h0  = blockIdx.y * 16;
    const int tid = threadIdx.x;

    for (int i = tid; i < 200; i += 256)
        wdw[i / 25][i % 25] = w_dw[(ch0 + i / 25) * 25 + i % 25];
    if (tid < 64) wpw[tid] = w_pw[g * 64 + tid];

    // zero the 8 edge columns of every (c, row)
    for (int i = tid; i < 8 * 20 * 8; i += 256) {
        int c = i / 160;
        int r = (i / 8) % 20;
        int e = i % 8;
        int col = (e < 4) ? e : (64 + e);   // 0..3, 68..71
        tile[c][r][col] = 0.f;
    }

    // interior: 8 ch x 20 rows x 16 float4 (coalesced)
    const float* base = qkv + ((size_t)b * TD3 + ch0) * NPIX;
    for (int i = tid; i < 8 * 20 * 16; i += 256) {
        int c   = i / 320;
        int rem = i % 320;
        int r   = rem / 16;
        int v4  = rem % 16;
        int gh  = h0 - 2 + r;
        float4 val = make_float4(0.f, 0.f, 0.f, 0.f);
        if (gh >= 0 && gh < HH)
            val = ((const float4*)(base + (size_t)c * NPIX + gh * WW))[v4];
        *(float4*)&tile[c][r][4 + v4 * 4] = val;
    }
    __syncthreads();

    const int ts = tid & 15;    // strip index: cols [ts*4, ts*4+4)
    const int ty = tid >> 4;    // output row 0..15
    const int x0 = ts * 4;      // global col of first output px

    float dwv[8][4];            // depthwise result per ch per px
#pragma unroll
    for (int c = 0; c < 8; c++) {
        float s0 = 0.f, s1 = 0.f, s2 = 0.f, s3 = 0.f;
#pragma unroll
        for (int i = 0; i < 5; i++) {
            // taps need tile cols [x0+2 .. x0+9]; load aligned [x0 .. x0+11]
            const float* rp = &tile[c][ty + i][x0];
            float4 a = *(const float4*)(rp);
            float4 bq = *(const float4*)(rp + 4);
            float4 cq = *(const float4*)(rp + 8);
            float v[12] = {a.x, a.y, a.z, a.w, bq.x, bq.y, bq.z, bq.w,
                           cq.x, cq.y, cq.z, cq.w};
#pragma unroll
            for (int j = 0; j < 5; j++) {
                float w = wdw[c][i * 5 + j];
                s0 += v[2 + j] * w;
                s1 += v[3 + j] * w;
                s2 += v[4 + j] * w;
                s3 += v[5 + j] * w;
            }
        }
        dwv[c][0] = s0; dwv[c][1] = s1; dwv[c][2] = s2; dwv[c][3] = s3;
    }

    float* obase = y + ((size_t)b * TD3 + ch0) * NPIX + (h0 + ty) * WW + x0;
#pragma unroll
    for (int o = 0; o < 8; o++) {
        float4 r = make_float4(0.f, 0.f, 0.f, 0.f);
#pragma unroll
        for (int i = 0; i < 8; i++) {
            float w = wpw[o * 8 + i];
            r.x += dwv[i][0] * w;
            r.y += dwv[i][1] * w;
            r.z += dwv[i][2] * w;
            r.w += dwv[i][3] * w;
        }
        *(float4*)(obase + (size_t)o * NPIX) = r;
    }
}

// ---------------------------------------------------------------------------
// Linear attention over 64 heads from one source tensor, float4-vectorized.
// ---------------------------------------------------------------------------
__global__ __launch_bounds__(256)
void attn_kernel(const float* __restrict__ src,
                 __half* __restrict__ att_h, __half* __restrict__ att_l,
                 int ch_out_base)
{
    const int b    = blockIdx.x >> 6;
    const int hloc = blockIdx.x & 63;
    const int tid  = threadIdx.x;

    const float* base = src + ((size_t)b * TD3 + hloc * 24) * NPIX;

    float acc[72];
#pragma unroll
    for (int i = 0; i < 72; i++) acc[i] = 0.f;

    for (int n4 = tid; n4 < NPIX / 4; n4 += 256) {
        float4 kk[8], vv[8];
#pragma unroll
        for (int e = 0; e < 8; e++) {
            float4 t = ((const float4*)(base + (size_t)(8 + e) * NPIX))[n4];
            kk[e] = make_float4(fmaxf(t.x, 0.f), fmaxf(t.y, 0.f),
                                fmaxf(t.z, 0.f), fmaxf(t.w, 0.f));
        }
#pragma unroll
        for (int d = 0; d < 8; d++)
            vv[d] = ((const float4*)(base + (size_t)(16 + d) * NPIX))[n4];
#pragma unroll
        for (int d = 0; d < 8; d++)
#pragma unroll
            for (int e = 0; e < 8; e++)
                acc[d * 8 + e] += vv[d].x * kk[e].x + vv[d].y * kk[e].y
                                + vv[d].z * kk[e].z + vv[d].w * kk[e].w;
#pragma unroll
        for (int e = 0; e < 8; e++)
            acc[64 + e] += kk[e].x + kk[e].y + kk[e].z + kk[e].w;
    }

    __shared__ float red[8][72];
    __shared__ float vk_s[72];
    const int lane = tid & 31, wid = tid >> 5;
#pragma unroll
    for (int i = 0; i < 72; i++) {
        float v = acc[i];
        v += __shfl_down_sync(0xffffffffu, v, 16);
        v += __shfl_down_sync(0xffffffffu, v, 8);
        v += __shfl_down_sync(0xffffffffu, v, 4);
        v += __shfl_down_sync(0xffffffffu, v, 2);
        v += __shfl_down_sync(0xffffffffu, v, 1);
        if (lane == 0) red[wid][i] = v;
    }
    __syncthreads();
    if (tid < 72) {
        float s = 0.f;
#pragma unroll
        for (int w = 0; w < 8; w++) s += red[w][tid];
        vk_s[tid] = s;
    }
    __syncthreads();

    float vk[72];
#pragma unroll
    for (int i = 0; i < 72; i++) vk[i] = vk_s[i];

    const size_t obase = ((size_t)b * 1024 + ch_out_base + hloc * 8) * NPIX;
    for (int n4 = tid; n4 < NPIX / 4; n4 += 256) {
        float4 q[8];
#pragma unroll
        for (int e = 0; e < 8; e++) {
            float4 t = ((const float4*)(base + (size_t)e * NPIX))[n4];
            q[e] = make_float4(fmaxf(t.x, 0.f), fmaxf(t.y, 0.f),
                               fmaxf(t.z, 0.f), fmaxf(t.w, 0.f));
        }
        float4 den = make_float4(0.f, 0.f, 0.f, 0.f);
#pragma unroll
        for (int e = 0; e < 8; e++) {
            den.x += vk[64 + e] * q[e].x; den.y += vk[64 + e] * q[e].y;
            den.z += vk[64 + e] * q[e].z; den.w += vk[64 + e] * q[e].w;
        }
        float4 inv = make_float4(1.f / (den.x + EPS_ATT), 1.f / (den.y + EPS_ATT),
                                 1.f / (den.z + EPS_ATT), 1.f / (den.w + EPS_ATT));
#pragma unroll
        for (int d = 0; d < 8; d++) {
            float4 num = make_float4(0.f, 0.f, 0.f, 0.f);
#pragma unroll
            for (int e = 0; e < 8; e++) {
                num.x += vk[d * 8 + e] * q[e].x; num.y += vk[d * 8 + e] * q[e].y;
                num.z += vk[d * 8 + e] * q[e].z; num.w += vk[d * 8 + e] * q[e].w;
            }
            float o0 = num.x * inv.x, o1 = num.y * inv.y;
            float o2 = num.z * inv.z, o3 = num.w * inv.w;
            __half h0 = __float2half(o0), h1 = __float2half(o1);
            __half h2 = __float2half(o2), h3 = __float2half(o3);
            __half2 hp0 = __halves2half2(h0, h1), hp1 = __halves2half2(h2, h3);
            __half2 lp0 = __halves2half2(__float2half(o0 - __half2float(h0)),
                                         __float2half(o1 - __half2float(h1)));
            __half2 lp1 = __halves2half2(__float2half(o2 - __half2float(h2)),
                                         __float2half(o3 - __half2float(h3)));
            size_t idx = obase + (size_t)d * NPIX + n4 * 4;
            __half2* ph = (__half2*)(att_h + idx);
            __half2* pl = (__half2*)(att_l + idx);
            ph[0] = hp0; ph[1] = hp1;
            pl[0] = lp0; pl[1] = lp1;
        }
    }
}

// ---------------------------------------------------------------------------
// Launch
// ---------------------------------------------------------------------------
extern "C" void kernel_launch(void* const* d_in, const int* in_sizes, int n_in,
                              void* d_out, int out_size)
{
    const float* x      = (const float*)d_in[0];
    const float* w_qkv  = (const float*)d_in[1];
    const float* w_dw   = (const float*)d_in[2];
    const float* w_pw   = (const float*)d_in[3];
    const float* w_proj = (const float*)d_in[4];
    const float* gamma  = (const float*)d_in[5];
    const float* beta   = (const float*)d_in[6];
    const float* mean   = (const float*)d_in[7];
    const float* var    = (const float*)d_in[8];
    float* out = (float*)d_out;

    float *qkv, *yb;
    __half *xh, *xl, *ath, *atl, *wqh, *wql, *wph, *wpl;
    cudaGetSymbolAddress((void**)&qkv, g_qkv);
    cudaGetSymbolAddress((void**)&yb,  g_y);
    cudaGetSymbolAddress((void**)&xh,  g_xh);
    cudaGetSymbolAddress((void**)&xl,  g_xl);
    cudaGetSymbolAddress((void**)&ath, g_ath);
    cudaGetSymbolAddress((void**)&atl, g_atl);
    cudaGetSymbolAddress((void**)&wqh, g_wqh);
    cudaGetSymbolAddress((void**)&wql, g_wql);
    cudaGetSymbolAddress((void**)&wph, g_wph);
    cudaGetSymbolAddress((void**)&wpl, g_wpl);

    static cudaStream_t s_side = nullptr;
    static cudaEvent_t ev_fork = nullptr, ev_join = nullptr;
    if (!s_side) {
        cudaStreamCreateWithFlags(&s_side, cudaStreamNonBlocking);
        cudaEventCreateWithFlags(&ev_fork, cudaEventDisableTiming);
        cudaEventCreateWithFlags(&ev_join, cudaEventDisableTiming);
        cudaFuncSetAttribute(mma_gemm<false>,
            cudaFuncAttributeMaxDynamicSharedMemorySize, DYN_SMEM);
        cudaFuncSetAttribute(mma_gemm<true>,
            cudaFuncAttributeMaxDynamicSharedMemorySize, DYN_SMEM);
    }

    // 0) splits for GEMM1 (main stream); w_proj split overlaps on side stream
    {
        int n4 = (B_SZ * C_IN * NPIX) / 4;
        split_kernel<<<(n4 + 255) / 256, 256>>>(x, xh, xl, n4);
        n4 = (TD3 * C_IN) / 4;
        split_kernel<<<(n4 + 255) / 256, 256>>>(w_qkv, wqh, wql, n4);
        n4 = (512 * 1024) / 4;
        split_kernel<<<(n4 + 255) / 256, 256, 0, s_side>>>(w_proj, wph, wpl, n4);
    }

    // 1) qkv = w_qkv @ x   (M=1536, N=4096, K=512 per batch), fp32 out
    mma_gemm<false><<<dim3(NPIX / 128, TD3 / 128, B_SZ), 128, DYN_SMEM>>>(
        wqh, wql, xh, xl, qkv, TD3, NPIX, C_IN,
        nullptr, nullptr, nullptr, nullptr);

    // fork: attn heads 0-63 (qkv only) overlaps dwpw
    cudaEventRecord(ev_fork, 0);
    cudaStreamWaitEvent(s_side, ev_fork, 0);
    attn_kernel<<<B_SZ * 64, 256, 0, s_side>>>(qkv, ath, atl, 0);

    // 2) y = grouped-pw(dwconv5x5(qkv)), 64x16 tiles
    dwpw_kernel<<<dim3(1, HH / 16, B_SZ * NGRP), 256>>>(
        qkv, w_dw, w_pw, yb);

    // 3) attn heads 64-127 (depends on y)
    attn_kernel<<<B_SZ * 64, 256>>>(yb, ath, atl, 512);

    // join side stream before GEMM2
    cudaEventRecord(ev_join, s_side);
    cudaStreamWaitEvent(0, ev_join, 0);

    // 4) out = BN(w_proj @ att)  (M=512, N=4096, K=1024 per batch)
    mma_gemm<true><<<dim3(NPIX / 128, 512 / 128, B_SZ), 128, DYN_SMEM>>>(
        wph, wpl, ath, atl, out, 512, NPIX, 1024,
        gamma, beta, mean, var);
}

// round 17
// speedup vs baseline: 1.0589x; 1.0004x over previous
#include <cuda_runtime.h>
#include <cuda_fp16.h>
#include <cstdint>
#include <cstddef>

// ---------------------------------------------------------------------------
// Problem constants
// ---------------------------------------------------------------------------
#define B_SZ   4
#define C_IN   512
#define TD3    1536          // 3*512
#define HH     64
#define WW     64
#define NPIX   4096          // 64*64
#define NGRP   192
#define NHEAD  128
#define EPS_ATT 1e-15f
#define EPS_BN  1e-5f

#define GSTAGES 3
#define ABYTES  8192                  // one operand chunk (128x32 or 32x128 fp16)
#define STAGE_BYTES (4 * ABYTES)      // Ah, Al, Bh, Bl
#define DYN_SMEM (GSTAGES * STAGE_BYTES)   // 96 KB  (x2 CTAs = 192 KB/SM)

// ---------------------------------------------------------------------------
// Scratch (device globals; no allocation allowed)
// ---------------------------------------------------------------------------
__device__ float   g_qkv[(size_t)B_SZ * TD3 * NPIX];    // fp32 [b][ch][n]
__device__ float   g_y  [(size_t)B_SZ * TD3 * NPIX];    // fp32 [b][ch][n]
__device__ __half  g_xh [(size_t)B_SZ * C_IN * NPIX];   // fp16 hi [b][c][n]
__device__ __half  g_xl [(size_t)B_SZ * C_IN * NPIX];   // fp16 lo
__device__ __half  g_ath[(size_t)B_SZ * 1024 * NPIX];   // att hi [b][ch][n]
__device__ __half  g_atl[(size_t)B_SZ * 1024 * NPIX];   // att lo
__device__ __half  g_wqh[TD3 * C_IN];
__device__ __half  g_wql[TD3 * C_IN];
__device__ __half  g_wph[512 * 1024];
__device__ __half  g_wpl[512 * 1024];

// ---------------------------------------------------------------------------
// helpers
// ---------------------------------------------------------------------------
__device__ __forceinline__ void ldsm_x4(uint32_t* r, uint32_t addr) {
    asm volatile("ldmatrix.sync.aligned.m8n8.x4.shared.b16 {%0,%1,%2,%3}, [%4];"
        : "=r"(r[0]), "=r"(r[1]), "=r"(r[2]), "=r"(r[3]) : "r"(addr));
}
__device__ __forceinline__ void ldsm_x4_t(uint32_t* r, uint32_t addr) {
    asm volatile("ldmatrix.sync.aligned.m8n8.x4.trans.shared.b16 {%0,%1,%2,%3}, [%4];"
        : "=r"(r[0]), "=r"(r[1]), "=r"(r[2]), "=r"(r[3]) : "r"(addr));
}
__device__ __forceinline__ void mma_f16(float* c, const uint32_t* a, const uint32_t* b) {
    asm volatile("mma.sync.aligned.m16n8k16.row.col.f32.f16.f16.f32 "
        "{%0,%1,%2,%3}, {%4,%5,%6,%7}, {%8,%9}, {%0,%1,%2,%3};"
        : "+f"(c[0]), "+f"(c[1]), "+f"(c[2]), "+f"(c[3])
        : "r"(a[0]), "r"(a[1]), "r"(a[2]), "r"(a[3]), "r"(b[0]), "r"(b[1]));
}
__device__ __forceinline__ void cp16(uint32_t smem, const void* g) {
    asm volatile("cp.async.cg.shared.global [%0], [%1], 16;" :: "r"(smem), "l"(g));
}
__device__ __forceinline__ void cp_commit() { asm volatile("cp.async.commit_group;"); }
template <int N>
__device__ __forceinline__ void cp_wait() { asm volatile("cp.async.wait_group %0;" :: "n"(N)); }

// byte offsets within one 8KB chunk
__device__ __forceinline__ uint32_t swA(int row, int ch) {      // 128 rows x 64B
    return (uint32_t)(row * 64 + ((ch ^ ((row >> 1) & 3)) << 4));
}
__device__ __forceinline__ uint32_t swB(int k, int ch) {        // 32 rows x 256B
    return (uint32_t)(k * 256 + ((ch ^ (k & 7)) << 4));
}

// ---------------------------------------------------------------------------
// fp16 3-term split tensor-core GEMM:
//   C[b] = Ah*Bh + Ah*Bl + Al*Bh   (A = weights MxK, B per-batch KxN)
// Block 128x128, K-tile 32, 128 threads (4 warps, warp tile 64x64).
// 3-stage cp.async ring, 2 CTAs/SM, single barrier per K-tile.
// ---------------------------------------------------------------------------
template <bool EPI>
__global__ __launch_bounds__(128, 2)
void mma_gemm(const __half* __restrict__ Ah, const __half* __restrict__ Al,
              const __half* __restrict__ Bhg, const __half* __restrict__ Blg,
              float* __restrict__ Cg, int M, int N, int K,
              const float* __restrict__ gamma, const float* __restrict__ beta,
              const float* __restrict__ mean,  const float* __restrict__ var)
{
    extern __shared__ __align__(16) char smem[];
    const uint32_t sbase = (uint32_t)__cvta_generic_to_shared(smem);

    const int tid  = threadIdx.x;
    const int lane = tid & 31;
    const int wid  = tid >> 5;
    const int warp_m = wid >> 1;   // 0..1  (64 rows)
    const int warp_n = wid & 1;    // 0..1  (64 cols)
    const int m0 = blockIdx.y * 128;
    const int n0 = blockIdx.x * 128;

    const __half* Bh = Bhg + (size_t)blockIdx.z * K * N;
    const __half* Bl = Blg + (size_t)blockIdx.z * K * N;
    float* Cp = Cg + (size_t)blockIdx.z * M * N;

    const int arow = tid >> 2, ach = tid & 3;    // 4 rows each (+0,+32,+64,+96)
    const int bk   = tid >> 4, bch = tid & 15;   // 4 k each   (+0,+8,+16,+24)

    float acc[4][8][4];
#pragma unroll
    for (int i = 0; i < 4; i++)
#pragma unroll
        for (int j = 0; j < 8; j++)
#pragma unroll
            for (int r = 0; r < 4; r++) acc[i][j][r] = 0.f;

    const int nkt = K / 32;

    auto prefetch = [&](int kt) {
        const uint32_t st = sbase + (kt % GSTAGES) * STAGE_BYTES;
#pragma unroll
        for (int i = 0; i < 4; i++) {
            size_t aoff = (size_t)(m0 + arow + i * 32) * K + kt * 32 + ach * 8;
            uint32_t ao = swA(arow + i * 32, ach);
            cp16(st + ao,          Ah + aoff);
            cp16(st + ABYTES + ao, Al + aoff);
            size_t boff = (size_t)(kt * 32 + bk + i * 8) * N + n0 + bch * 8;
            uint32_t bo = swB(bk + i * 8, bch);
            cp16(st + 2 * ABYTES + bo, Bh + boff);
            cp16(st + 3 * ABYTES + bo, Bl + boff);
        }
        cp_commit();
    };

    prefetch(0);
    prefetch(1);

    for (int kt = 0; kt < nkt; ++kt) {
        cp_wait<GSTAGES - 2>();
        __syncthreads();

        const uint32_t st  = sbase + (kt % GSTAGES) * STAGE_BYTES;
        const uint32_t aAh = st;
        const uint32_t aAl = st + ABYTES;
        const uint32_t aBh = st + 2 * ABYTES;
        const uint32_t aBl = st + 3 * ABYTES;

#pragma unroll
        for (int kk = 0; kk < 2; ++kk) {
            const int kcol = kk * 16;
            uint32_t bh[4][4], bl[4][4];
#pragma unroll
            for (int p = 0; p < 4; p++) {
                int k = kcol + ((lane >> 3) & 1) * 8 + (lane & 7);
                int n = warp_n * 64 + p * 16 + (lane >> 4) * 8;
                uint32_t off = swB(k, n >> 3);
                ldsm_x4_t(bh[p], aBh + off);
                ldsm_x4_t(bl[p], aBl + off);
            }
#pragma unroll
            for (int mf = 0; mf < 4; mf++) {
                uint32_t ah[4], al[4];
                int row = warp_m * 64 + mf * 16 + ((lane >> 3) & 1) * 8 + (lane & 7);
                int ch  = (kcol >> 3) + (lane >> 4);
                uint32_t off = swA(row, ch);
                ldsm_x4(ah, aAh + off);
                ldsm_x4(al, aAl + off);
#pragma unroll
                for (int nf = 0; nf < 8; nf++) {
                    const uint32_t* ph = &bh[nf >> 1][(nf & 1) * 2];
                    const uint32_t* pl = &bl[nf >> 1][(nf & 1) * 2];
                    mma_f16(acc[mf][nf], ah, ph);
                    mma_f16(acc[mf][nf], ah, pl);
                    mma_f16(acc[mf][nf], al, ph);
                }
            }
            if (kk == 0) {
                if (kt + GSTAGES - 1 < nkt) prefetch(kt + GSTAGES - 1);
                else cp_commit();
            }
        }
        // single barrier per K-tile: next iteration's top barrier orders reuse
    }

    // epilogue
#pragma unroll
    for (int mf = 0; mf < 4; mf++) {
        int r0 = m0 + warp_m * 64 + mf * 16 + (lane >> 2);
        float s0 = 1.f, t0 = 0.f, s1 = 1.f, t1 = 0.f;
        if (EPI) {
            float iv0 = rsqrtf(var[r0] + EPS_BN);
            s0 = gamma[r0] * iv0; t0 = beta[r0] - mean[r0] * s0;
            float iv1 = rsqrtf(var[r0 + 8] + EPS_BN);
            s1 = gamma[r0 + 8] * iv1; t1 = beta[r0 + 8] - mean[r0 + 8] * s1;
        }
#pragma unroll
        for (int nf = 0; nf < 8; nf++) {
            int c = n0 + warp_n * 64 + nf * 8 + (lane & 3) * 2;
            float* p0 = Cp + (size_t)r0 * N + c;
            float* p1 = Cp + (size_t)(r0 + 8) * N + c;
            float2 v0, v1;
            if (EPI) {
                v0 = make_float2(acc[mf][nf][0] * s0 + t0, acc[mf][nf][1] * s0 + t0);
                v1 = make_float2(acc[mf][nf][2] * s1 + t1, acc[mf][nf][3] * s1 + t1);
            } else {
                v0 = make_float2(acc[mf][nf][0], acc[mf][nf][1]);
                v1 = make_float2(acc[mf][nf][2], acc[mf][nf][3]);
            }
            *(float2*)p0 = v0;
            *(float2*)p1 = v1;
        }
    }
}

// ---------------------------------------------------------------------------
// fp32 -> fp16 hi/lo split (x4)
// ---------------------------------------------------------------------------
__global__ void split_kernel(const float* __restrict__ in,
                             __half* __restrict__ h, __half* __restrict__ l, int n4)
{
    int i = blockIdx.x * 256 + threadIdx.x;
    if (i >= n4) return;
    float4 v = ((const float4*)in)[i];
    __half h0 = __float2half(v.x), h1 = __float2half(v.y);
    __half h2 = __float2half(v.z), h3 = __float2half(v.w);
    ((__half2*)h)[i * 2]     = __halves2half2(h0, h1);
    ((__half2*)h)[i * 2 + 1] = __halves2half2(h2, h3);
    ((__half2*)l)[i * 2]     = __halves2half2(__float2half(v.x - __half2float(h0)),
                                              __float2half(v.y - __half2float(h1)));
    ((__half2*)l)[i * 2 + 1] = __halves2half2(__float2half(v.z - __half2float(h2)),
                                              __float2half(v.w - __half2float(h3)));
}

// ---------------------------------------------------------------------------
// Fused depthwise 5x5 (pad 2) + grouped 8x8 pointwise.
// 16-row tiles, 4-pixel register strips, LDS.128 tap loads.
// ---------------------------------------------------------------------------
__global__ __launch_bounds__(256)
void dwpw_kernel(const float* __restrict__ qkv, const float* __restrict__ w_dw,
                 const float* __restrict__ w_pw, float* __restrict__ y)
{
    __shared__ float tile[8][20][72];   // data cols [4..67], zeros at edges
    __shared__ float wdw[8][25];
    __shared__ float wpw[64];

    const int b   = blockIdx.z / NGRP;
    const int g   = blockIdx.z % NGRP;
    const int ch0 = g * 8;
    const int h0  = blockIdx.y * 16;
    const int tid = threadIdx.x;

    for (int i = tid; i < 200; i += 256)
        wdw[i / 25][i % 25] = w_dw[(ch0 + i / 25) * 25 + i % 25];
    if (tid < 64) wpw[tid] = w_pw[g * 64 + tid];

    for (int i = tid; i < 8 * 20 * 8; i += 256) {
        int c = i / 160;
        int r = (i / 8) % 20;
        int e = i % 8;
        int col = (e < 4) ? e : (64 + e);   // 0..3, 68..71
        tile[c][r][col] = 0.f;
    }

    const float* base = qkv + ((size_t)b * TD3 + ch0) * NPIX;
    for (int i = tid; i < 8 * 20 * 16; i += 256) {
        int c   = i / 320;
        int rem = i % 320;
        int r   = rem / 16;
        int v4  = rem % 16;
        int gh  = h0 - 2 + r;
        float4 val = make_float4(0.f, 0.f, 0.f, 0.f);
        if (gh >= 0 && gh < HH)
            val = ((const float4*)(base + (size_t)c * NPIX + gh * WW))[v4];
        *(float4*)&tile[c][r][4 + v4 * 4] = val;
    }
    __syncthreads();

    const int ts = tid & 15;    // strip index: cols [ts*4, ts*4+4)
    const int ty = tid >> 4;    // output row 0..15
    const int x0 = ts * 4;

    float dwv[8][4];
#pragma unroll
    for (int c = 0; c < 8; c++) {
        float s0 = 0.f, s1 = 0.f, s2 = 0.f, s3 = 0.f;
#pragma unroll
        for (int i = 0; i < 5; i++) {
            const float* rp = &tile[c][ty + i][x0];
            float4 a = *(const float4*)(rp);
            float4 bq = *(const float4*)(rp + 4);
            float4 cq = *(const float4*)(rp + 8);
            float v[12] = {a.x, a.y, a.z, a.w, bq.x, bq.y, bq.z, bq.w,
                           cq.x, cq.y, cq.z, cq.w};
#pragma unroll
            for (int j = 0; j < 5; j++) {
                float w = wdw[c][i * 5 + j];
                s0 += v[2 + j] * w;
                s1 += v[3 + j] * w;
                s2 += v[4 + j] * w;
                s3 += v[5 + j] * w;
            }
        }
        dwv[c][0] = s0; dwv[c][1] = s1; dwv[c][2] = s2; dwv[c][3] = s3;
    }

    float* obase = y + ((size_t)b * TD3 + ch0) * NPIX + (h0 + ty) * WW + x0;
#pragma unroll
    for (int o = 0; o < 8; o++) {
        float4 r = make_float4(0.f, 0.f, 0.f, 0.f);
#pragma unroll
        for (int i = 0; i < 8; i++) {
            float w = wpw[o * 8 + i];
            r.x += dwv[i][0] * w;
            r.y += dwv[i][1] * w;
            r.z += dwv[i][2] * w;
            r.w += dwv[i][3] * w;
        }
        *(float4*)(obase + (size_t)o * NPIX) = r;
    }
}

// ---------------------------------------------------------------------------
// Linear attention over 64 heads from one source tensor, float4-vectorized.
// 512 threads/block for deeper MLP / latency hiding.
// ---------------------------------------------------------------------------
__global__ __launch_bounds__(512)
void attn_kernel(const float* __restrict__ src,
                 __half* __restrict__ att_h, __half* __restrict__ att_l,
                 int ch_out_base)
{
    const int b    = blockIdx.x >> 6;
    const int hloc = blockIdx.x & 63;
    const int tid  = threadIdx.x;

    const float* base = src + ((size_t)b * TD3 + hloc * 24) * NPIX;

    float acc[72];
#pragma unroll
    for (int i = 0; i < 72; i++) acc[i] = 0.f;

    for (int n4 = tid; n4 < NPIX / 4; n4 += 512) {
        float4 kk[8], vv[8];
#pragma unroll
        for (int e = 0; e < 8; e++) {
            float4 t = ((const float4*)(base + (size_t)(8 + e) * NPIX))[n4];
            kk[e] = make_float4(fmaxf(t.x, 0.f), fmaxf(t.y, 0.f),
                                fmaxf(t.z, 0.f), fmaxf(t.w, 0.f));
        }
#pragma unroll
        for (int d = 0; d < 8; d++)
            vv[d] = ((const float4*)(base + (size_t)(16 + d) * NPIX))[n4];
#pragma unroll
        for (int d = 0; d < 8; d++)
#pragma unroll
            for (int e = 0; e < 8; e++)
                acc[d * 8 + e] += vv[d].x * kk[e].x + vv[d].y * kk[e].y
                                + vv[d].z * kk[e].z + vv[d].w * kk[e].w;
#pragma unroll
        for (int e = 0; e < 8; e++)
            acc[64 + e] += kk[e].x + kk[e].y + kk[e].z + kk[e].w;
    }

    __shared__ float red[16][72];
    __shared__ float vk_s[72];
    const int lane = tid & 31, wid = tid >> 5;
#pragma unroll
    for (int i = 0; i < 72; i++) {
        float v = acc[i];
        v += __shfl_down_sync(0xffffffffu, v, 16);
        v += __shfl_down_sync(0xffffffffu, v, 8);
        v += __shfl_down_sync(0xffffffffu, v, 4);
        v += __shfl_down_sync(0xffffffffu, v, 2);
        v += __shfl_down_sync(0xffffffffu, v, 1);
        if (lane == 0) red[wid][i] = v;
    }
    __syncthreads();
    if (tid < 72) {
        float s = 0.f;
#pragma unroll
        for (int w = 0; w < 16; w++) s += red[w][tid];
        vk_s[tid] = s;
    }
    __syncthreads();

    float vk[72];
#pragma unroll
    for (int i = 0; i < 72; i++) vk[i] = vk_s[i];

    const size_t obase = ((size_t)b * 1024 + ch_out_base + hloc * 8) * NPIX;
    for (int n4 = tid; n4 < NPIX / 4; n4 += 512) {
        float4 q[8];
#pragma unroll
        for (int e = 0; e < 8; e++) {
            float4 t = ((const float4*)(base + (size_t)e * NPIX))[n4];
            q[e] = make_float4(fmaxf(t.x, 0.f), fmaxf(t.y, 0.f),
                               fmaxf(t.z, 0.f), fmaxf(t.w, 0.f));
        }
        float4 den = make_float4(0.f, 0.f, 0.f, 0.f);
#pragma unroll
        for (int e = 0; e < 8; e++) {
            den.x += vk[64 + e] * q[e].x; den.y += vk[64 + e] * q[e].y;
            den.z += vk[64 + e] * q[e].z; den.w += vk[64 + e] * q[e].w;
        }
        float4 inv = make_float4(1.f / (den.x + EPS_ATT), 1.f / (den.y + EPS_ATT),
                                 1.f / (den.z + EPS_ATT), 1.f / (den.w + EPS_ATT));
#pragma unroll
        for (int d = 0; d < 8; d++) {
            float4 num = make_float4(0.f, 0.f, 0.f, 0.f);
#pragma unroll
            for (int e = 0; e < 8; e++) {
                num.x += vk[d * 8 + e] * q[e].x; num.y += vk[d * 8 + e] * q[e].y;
                num.z += vk[d * 8 + e] * q[e].z; num.w += vk[d * 8 + e] * q[e].w;
            }
            float o0 = num.x * inv.x, o1 = num.y * inv.y;
            float o2 = num.z * inv.z, o3 = num.w * inv.w;
            __half h0 = __float2half(o0), h1 = __float2half(o1);
            __half h2 = __float2half(o2), h3 = __float2half(o3);
            __half2 hp0 = __halves2half2(h0, h1), hp1 = __halves2half2(h2, h3);
            __half2 lp0 = __halves2half2(__float2half(o0 - __half2float(h0)),
                                         __float2half(o1 - __half2float(h1)));
            __half2 lp1 = __halves2half2(__float2half(o2 - __half2float(h2)),
                                         __float2half(o3 - __half2float(h3)));
            size_t idx = obase + (size_t)d * NPIX + n4 * 4;
            __half2* ph = (__half2*)(att_h + idx);
            __half2* pl = (__half2*)(att_l + idx);
            ph[0] = hp0; ph[1] = hp1;
            pl[0] = lp0; pl[1] = lp1;
        }
    }
}

// ---------------------------------------------------------------------------
// Launch
// ---------------------------------------------------------------------------
extern "C" void kernel_launch(void* const* d_in, const int* in_sizes, int n_in,
                              void* d_out, int out_size)
{
    const float* x      = (const float*)d_in[0];
    const float* w_qkv  = (const float*)d_in[1];
    const float* w_dw   = (const float*)d_in[2];
    const float* w_pw   = (const float*)d_in[3];
    const float* w_proj = (const float*)d_in[4];
    const float* gamma  = (const float*)d_in[5];
    const float* beta   = (const float*)d_in[6];
    const float* mean   = (const float*)d_in[7];
    const float* var    = (const float*)d_in[8];
    float* out = (float*)d_out;

    float *qkv, *yb;
    __half *xh, *xl, *ath, *atl, *wqh, *wql, *wph, *wpl;
    cudaGetSymbolAddress((void**)&qkv, g_qkv);
    cudaGetSymbolAddress((void**)&yb,  g_y);
    cudaGetSymbolAddress((void**)&xh,  g_xh);
    cudaGetSymbolAddress((void**)&xl,  g_xl);
    cudaGetSymbolAddress((void**)&ath, g_ath);
    cudaGetSymbolAddress((void**)&atl, g_atl);
    cudaGetSymbolAddress((void**)&wqh, g_wqh);
    cudaGetSymbolAddress((void**)&wql, g_wql);
    cudaGetSymbolAddress((void**)&wph, g_wph);
    cudaGetSymbolAddress((void**)&wpl, g_wpl);

    static cudaStream_t s_side = nullptr;
    static cudaEvent_t ev_fork = nullptr, ev_join = nullptr;
    if (!s_side) {
        cudaStreamCreateWithFlags(&s_side, cudaStreamNonBlocking);
        cudaEventCreateWithFlags(&ev_fork, cudaEventDisableTiming);
        cudaEventCreateWithFlags(&ev_join, cudaEventDisableTiming);
        cudaFuncSetAttribute(mma_gemm<false>,
            cudaFuncAttributeMaxDynamicSharedMemorySize, DYN_SMEM);
        cudaFuncSetAttribute(mma_gemm<true>,
            cudaFuncAttributeMaxDynamicSharedMemorySize, DYN_SMEM);
    }

    // 0) splits for GEMM1 (main stream); w_proj split overlaps on side stream
    {
        int n4 = (B_SZ * C_IN * NPIX) / 4;
        split_kernel<<<(n4 + 255) / 256, 256>>>(x, xh, xl, n4);
        n4 = (TD3 * C_IN) / 4;
        split_kernel<<<(n4 + 255) / 256, 256>>>(w_qkv, wqh, wql, n4);
        n4 = (512 * 1024) / 4;
        split_kernel<<<(n4 + 255) / 256, 256, 0, s_side>>>(w_proj, wph, wpl, n4);
    }

    // 1) qkv = w_qkv @ x   (M=1536, N=4096, K=512 per batch), fp32 out
    mma_gemm<false><<<dim3(NPIX / 128, TD3 / 128, B_SZ), 128, DYN_SMEM>>>(
        wqh, wql, xh, xl, qkv, TD3, NPIX, C_IN,
        nullptr, nullptr, nullptr, nullptr);

    // fork: attn heads 0-63 (qkv only) overlaps dwpw
    cudaEventRecord(ev_fork, 0);
    cudaStreamWaitEvent(s_side, ev_fork, 0);
    attn_kernel<<<B_SZ * 64, 512, 0, s_side>>>(qkv, ath, atl, 0);

    // 2) y = grouped-pw(dwconv5x5(qkv)), 64x16 tiles
    dwpw_kernel<<<dim3(1, HH / 16, B_SZ * NGRP), 256>>>(
        qkv, w_dw, w_pw, yb);

    // 3) attn heads 64-127 (depends on y)
    attn_kernel<<<B_SZ * 64, 512>>>(yb, ath, atl, 512);

    // join side stream before GEMM2
    cudaEventRecord(ev_join, s_side);
    cudaStreamWaitEvent(0, ev_join, 0);

    // 4) out = BN(w_proj @ att)  (M=512, N=4096, K=1024 per batch)
    mma_gemm<true><<<dim3(NPIX / 128, 512 / 128, B_SZ), 128, DYN_SMEM>>>(
        wph, wpl, ath, atl, out, 512, NPIX, 1024,
        gamma, beta, mean, var);
}